// round 7
// baseline (speedup 1.0000x reference)
#include <cuda_runtime.h>

#define NTHR 256
#define NBLK 1184                        // 8 blocks/SM x 148 SMs = one full wave

__device__ float        g_partials[NBLK];
__device__ unsigned int g_count = 0;

// Raw MUFU.LG2 — inputs guaranteed in [1e-4, 1-1e-4] (always normal), so no
// denormal fixup needed. One instruction per log.
__device__ __forceinline__ float lg2_raw(float x) {
    float r;
    asm("lg2.approx.ftz.f32 %0, %1;" : "=f"(r) : "f"(x));
    return r;
}

// Binary KL in log2 units (sum scaled by ln2 once at the end).
// ~11 instructions/element: 2 FADD + 4 MUFU + 2 FSUB + 2 FMA.
__device__ __forceinline__ void kl2_acc(float p, float q, float& acc) {
    float omp = 1.0f - p;
    float omq = 1.0f - q;
    float d1  = lg2_raw(p)   - lg2_raw(q);
    float d2  = lg2_raw(omp) - lg2_raw(omq);
    acc = fmaf(p,   d1, acc);
    acc = fmaf(omp, d2, acc);
}

__global__ void __launch_bounds__(NTHR, 8)   // cap 32 regs -> 64 warps/SM
kl_fused(const float* __restrict__ p, const float* __restrict__ q,
         int n, float* __restrict__ out) {
    const int nvec = n >> 2;
    const float4* __restrict__ p4 = reinterpret_cast<const float4*>(p);
    const float4* __restrict__ q4 = reinterpret_cast<const float4*>(q);

    float acc = 0.0f;   // log2 units

    // Simple grid-stride: minimal live registers; latency hidden by
    // 16 warps/SMSP rather than software pipelining.
    const int stride = NBLK * NTHR;
    for (int i = blockIdx.x * NTHR + threadIdx.x; i < nvec; i += stride) {
        float4 a = __ldcs(&p4[i]);
        float4 b = __ldcs(&q4[i]);
        kl2_acc(a.x, b.x, acc);
        kl2_acc(a.y, b.y, acc);
        kl2_acc(a.z, b.z, acc);
        kl2_acc(a.w, b.w, acc);
    }

    // Scalar tail (n % 4): last block only.
    if (blockIdx.x == gridDim.x - 1) {
        for (int i = (nvec << 2) + threadIdx.x; i < n; i += NTHR)
            kl2_acc(p[i], q[i], acc);
    }

    acc *= 0.6931471805599453f;   // log2 -> ln, once per thread

    // Block reduce
    #pragma unroll
    for (int o = 16; o > 0; o >>= 1)
        acc += __shfl_down_sync(0xffffffffu, acc, o);
    __shared__ float s[NTHR / 32];
    if ((threadIdx.x & 31) == 0) s[threadIdx.x >> 5] = acc;
    __syncthreads();
    float bsum = 0.0f;
    if (threadIdx.x < 32) {
        bsum = (threadIdx.x < NTHR / 32) ? s[threadIdx.x] : 0.0f;
        #pragma unroll
        for (int o = (NTHR / 64); o > 0; o >>= 1)
            bsum += __shfl_down_sync(0xffffffffu, bsum, o);
    }

    __shared__ bool is_last;
    if (threadIdx.x == 0) {
        g_partials[blockIdx.x] = bsum;
        __threadfence();
        // atomicInc wraps to 0 at gridDim.x-1 -> self-resetting, graph-replay safe.
        unsigned int done = atomicInc(&g_count, gridDim.x - 1);
        is_last = (done == gridDim.x - 1);
    }
    __syncthreads();

    if (is_last) {
        // Deterministic fixed-order final reduce in fp64.
        double dacc = 0.0;
        for (int i = threadIdx.x; i < gridDim.x; i += NTHR)
            dacc += (double)g_partials[i];
        #pragma unroll
        for (int o = 16; o > 0; o >>= 1)
            dacc += __shfl_down_sync(0xffffffffu, dacc, o);
        __shared__ double sd[NTHR / 32];
        if ((threadIdx.x & 31) == 0) sd[threadIdx.x >> 5] = dacc;
        __syncthreads();
        if (threadIdx.x == 0) {
            double t = 0.0;
            #pragma unroll
            for (int w = 0; w < NTHR / 32; w++) t += sd[w];
            out[0] = (float)t;
        }
    }
}

extern "C" void kernel_launch(void* const* d_in, const int* in_sizes, int n_in,
                              void* d_out, int out_size) {
    const float* p = (const float*)d_in[0];
    const float* q = (const float*)d_in[1];
    float* out = (float*)d_out;
    int n = in_sizes[0];

    kl_fused<<<NBLK, NTHR>>>(p, q, n, out);
}